// round 4
// baseline (speedup 1.0000x reference)
#include <cuda_runtime.h>

// Problem constants (from reference)
#define NN 64
#define CC 256
#define EMBED 16
#define INDEX_K 16              // ceil(256^0.5) = 16
#define HW 3136                 // 56*56
#define HW4 784                 // float4 per (n,c) slab
#define SCALE (256.0f / 240.0f) // c / (c - INDEX)

#define GCH 16                  // channels per block
#define GF4 (GCH * HW4)         // 12544 float4 per block = 49 * 256
#define NBLK (NN * (CC / GCH))  // 1024 blocks

// One block = 16 contiguous channels of one sample.
// Mask for ALL 256 channels computed once per block (amortized 16x),
// then a pure float4 stream over 49*256 elements.
__global__ void __launch_bounds__(256, 7)
fused_kernel(const float4* __restrict__ x,
             const float* __restrict__ embeds,
             const float* __restrict__ table,
             float4* __restrict__ out) {
    __shared__ float s_act[CC];
    __shared__ float s_mult[CC];

    const int n  = blockIdx.x >> 4;        // sample
    const int c0 = (blockIdx.x & 15) << 4; // first channel of this group
    const int t  = threadIdx.x;

    const long long base = ((long long)(n * CC + c0)) * HW4;
    const float4* __restrict__ xin = x + base;
    float4* __restrict__ o = out + base;

    // ---- front-batch first 4 rounds of DRAM loads (start DRAM at cycle 0) ----
    float4 p0 = xin[t];
    float4 p1 = xin[t + 256];
    float4 p2 = xin[t + 512];
    float4 p3 = xin[t + 768];

    // ---- mask: activ[n][t] for all 256 channels, rank via smem scan ----
    float a = 0.0f;
#pragma unroll
    for (int e = 0; e < EMBED; ++e) {
        a += __ldg(embeds + n * EMBED + e) * __ldg(table + e * CC + t);
    }
    s_act[t] = a;
    __syncthreads();
    int cnt = 0;
#pragma unroll 8
    for (int j = 0; j < CC; ++j) {
        cnt += (s_act[j] <= a) ? 1 : 0;
    }
    // keep <=> rank count >= INDEX_K+1 (tie-safe; == sorted[16] <= activ[c])
    s_mult[t] = (cnt >= INDEX_K + 1) ? SCALE : 0.0f;
    __syncthreads();

    // ---- drain prefetched rounds (i = 0..3) ----
    {
        float m0 = s_mult[c0 + (t) / HW4];
        float m1 = s_mult[c0 + (t + 256) / HW4];
        float m2 = s_mult[c0 + (t + 512) / HW4];
        float m3 = s_mult[c0 + (t + 768) / HW4];
        p0.x *= m0; p0.y *= m0; p0.z *= m0; p0.w *= m0;
        p1.x *= m1; p1.y *= m1; p1.z *= m1; p1.w *= m1;
        p2.x *= m2; p2.y *= m2; p2.z *= m2; p2.w *= m2;
        p3.x *= m3; p3.y *= m3; p3.z *= m3; p3.w *= m3;
        o[t]       = p0;
        o[t + 256] = p1;
        o[t + 512] = p2;
        o[t + 768] = p3;
    }

    // ---- main stream: rounds 4..47 in batches of 4 (MLP=4), then round 48 ----
    for (int i = 4; i < 48; i += 4) {
        const int i0 = i * 256 + t;
        float4 v0 = xin[i0];
        float4 v1 = xin[i0 + 256];
        float4 v2 = xin[i0 + 512];
        float4 v3 = xin[i0 + 768];
        const float m0 = s_mult[c0 + (i0) / HW4];
        const float m1 = s_mult[c0 + (i0 + 256) / HW4];
        const float m2 = s_mult[c0 + (i0 + 512) / HW4];
        const float m3 = s_mult[c0 + (i0 + 768) / HW4];
        v0.x *= m0; v0.y *= m0; v0.z *= m0; v0.w *= m0;
        v1.x *= m1; v1.y *= m1; v1.z *= m1; v1.w *= m1;
        v2.x *= m2; v2.y *= m2; v2.z *= m2; v2.w *= m2;
        v3.x *= m3; v3.y *= m3; v3.z *= m3; v3.w *= m3;
        o[i0]       = v0;
        o[i0 + 256] = v1;
        o[i0 + 512] = v2;
        o[i0 + 768] = v3;
    }
    {
        const int i0 = 48 * 256 + t;
        float4 v = xin[i0];
        const float m = s_mult[c0 + i0 / HW4];
        v.x *= m; v.y *= m; v.z *= m; v.w *= m;
        o[i0] = v;
    }
}

extern "C" void kernel_launch(void* const* d_in, const int* in_sizes, int n_in,
                              void* d_out, int out_size) {
    const float* x      = (const float*)d_in[0];  // [64,256,56,56]
    const float* embeds = (const float*)d_in[1];  // [64,16]
    const float* table  = (const float*)d_in[2];  // [16,256]
    float* out = (float*)d_out;

    fused_kernel<<<NBLK, 256>>>((const float4*)x, embeds, table, (float4*)out);
}

// round 5
// speedup vs baseline: 1.0974x; 1.0974x over previous
#include <cuda_runtime.h>

// Problem constants (from reference)
#define NN 64
#define CC 256
#define EMBED 16
#define INDEX_K 16              // ceil(256^0.5) = 16
#define HW4 784                 // float4 per (n,c) slab (56*56/4)
#define SCALE (256.0f / 240.0f) // c / (c - INDEX)

#define GCH 4                   // channels per block
#define NBLK (NN * CC / GCH)    // 4096 blocks

// One block = 4 contiguous channels of one sample (4*784 = 3136 float4).
// Mask: thread t computes activ[n][t]; the block's 4 multipliers come from
// 4 __syncthreads_count reductions (no smem scan, no divisions anywhere).
__global__ void __launch_bounds__(256)
fused_kernel(const float4* __restrict__ x,
             const float* __restrict__ embeds,
             const float* __restrict__ table,
             float4* __restrict__ out) {
    __shared__ float s_act[CC];

    const int blk = blockIdx.x;
    const int n  = blk >> 6;          // 64 channel-groups per sample
    const int c0 = (blk & 63) << 2;   // first channel of this group
    const int t  = threadIdx.x;

    const long long base = ((long long)(n * CC + c0)) * HW4;
    const float4* __restrict__ xin = x + base;
    float4* __restrict__ o = out + base;

    // ---- front-batch channel-0 DRAM loads (start HBM at cycle 0) ----
    float4 p0 = xin[t];
    float4 p1 = xin[t + 256];
    float4 p2 = xin[t + 512];

    // ---- mask (overlapped under the loads above) ----
    float a = 0.0f;
#pragma unroll
    for (int e = 0; e < EMBED; ++e) {
        a += __ldg(embeds + n * EMBED + e) * __ldg(table + e * CC + t);
    }
    s_act[t] = a;
    __syncthreads();
    const float ac0 = s_act[c0];
    const float ac1 = s_act[c0 + 1];
    const float ac2 = s_act[c0 + 2];
    const float ac3 = s_act[c0 + 3];
    // keep <=> #{j: activ[j] <= activ[c]} >= INDEX_K+1 (tie-safe == sorted[16] <= activ[c])
    const float m0 = (__syncthreads_count(a <= ac0) >= INDEX_K + 1) ? SCALE : 0.0f;
    const float m1 = (__syncthreads_count(a <= ac1) >= INDEX_K + 1) ? SCALE : 0.0f;
    const float m2 = (__syncthreads_count(a <= ac2) >= INDEX_K + 1) ? SCALE : 0.0f;
    const float m3 = (__syncthreads_count(a <= ac3) >= INDEX_K + 1) ? SCALE : 0.0f;

    // ---- channel 0: drain prefetched rounds ----
    p0.x *= m0; p0.y *= m0; p0.z *= m0; p0.w *= m0;
    p1.x *= m0; p1.y *= m0; p1.z *= m0; p1.w *= m0;
    p2.x *= m0; p2.y *= m0; p2.z *= m0; p2.w *= m0;
    o[t]       = p0;
    o[t + 256] = p1;
    o[t + 512] = p2;

    // ---- channels 1..3: 3 full rounds each, constant offsets ----
#define DO_CH(K, M)                                                        \
    {                                                                      \
        float4 v0 = xin[(K)*HW4 + t];                                      \
        float4 v1 = xin[(K)*HW4 + t + 256];                                \
        float4 v2 = xin[(K)*HW4 + t + 512];                                \
        v0.x *= (M); v0.y *= (M); v0.z *= (M); v0.w *= (M);                \
        v1.x *= (M); v1.y *= (M); v1.z *= (M); v1.w *= (M);                \
        v2.x *= (M); v2.y *= (M); v2.z *= (M); v2.w *= (M);                \
        o[(K)*HW4 + t]       = v0;                                         \
        o[(K)*HW4 + t + 256] = v1;                                         \
        o[(K)*HW4 + t + 512] = v2;                                         \
    }
    DO_CH(1, m1)
    DO_CH(2, m2)
    DO_CH(3, m3)
#undef DO_CH

    // ---- fused tail: 4 channels x 16 float4 (indices 768..783) ----
    if (t < 64) {
        const int ch  = t >> 4;                 // 0..3
        const int idx = ch * HW4 + 768 + (t & 15);
        const float m = (ch == 0) ? m0 : (ch == 1) ? m1 : (ch == 2) ? m2 : m3;
        float4 v = xin[idx];
        v.x *= m; v.y *= m; v.z *= m; v.w *= m;
        o[idx] = v;
    }
}

extern "C" void kernel_launch(void* const* d_in, const int* in_sizes, int n_in,
                              void* d_out, int out_size) {
    const float* x      = (const float*)d_in[0];  // [64,256,56,56]
    const float* embeds = (const float*)d_in[1];  // [64,16]
    const float* table  = (const float*)d_in[2];  // [16,256]
    float* out = (float*)d_out;

    fused_kernel<<<NBLK, 256>>>((const float4*)x, embeds, table, (float4*)out);
}